// round 15
// baseline (speedup 1.0000x reference)
#include <cuda_runtime.h>
#include <cuda_bf16.h>

#define TPB 256
#define MAX_ATOMS 100000
#define NB 64
#define NB2 32   // batch pairs per atom
#define NWARP (TPB / 32)
#define TR_ATOMS 32
// Per-atom block: 32 x float4 (xy pairs, 512B) + 32 x float2 (z pairs, 256B)
#define ATOM_STRIDE4 48

// Batch-fastest positions, 2-load layout:
//  [atom] : f4[lane] = (x_lo, x_hi, y_lo, y_hi), then f2[lane] = (z_lo, z_hi)
__device__ float4 g_pos4[(size_t)MAX_ATOMS * ATOM_STRIDE4];

// Tiled transpose: pos[b][atom][3] -> packed layout above. Zeroes out[].
__global__ void transpose_kernel(const float* __restrict__ pos, int n_atoms,
                                 float* __restrict__ out) {
    __shared__ float tile[NB][TR_ATOMS * 3 + 1];   // [64][97]
    int tid = threadIdx.x;
    int atom_base = blockIdx.x * TR_ATOMS;

    if (blockIdx.x == 0 && tid < NB) out[tid] = 0.0f;

    int lim3 = n_atoms * 3;
    int base3 = atom_base * 3;
    #pragma unroll
    for (int idx = tid; idx < NB * (TR_ATOMS * 3 / 4); idx += TPB) {
        int b = idx / (TR_ATOMS * 3 / 4);
        int q = idx - b * (TR_ATOMS * 3 / 4);
        int g = base3 + q * 4;
        if (g + 3 < lim3) {
            float4 v = __ldg((const float4*)(pos + (size_t)b * lim3 + g));
            tile[b][q * 4]     = v.x;
            tile[b][q * 4 + 1] = v.y;
            tile[b][q * 4 + 2] = v.z;
            tile[b][q * 4 + 3] = v.w;
        } else {
            for (int k = 0; k < 4 && g + k < lim3; k++)
                tile[b][q * 4 + k] = __ldg(&pos[(size_t)b * lim3 + g + k]);
        }
    }
    __syncthreads();
    // write: one (atom, lane) pair per iteration -> 1 STG.128 + 1 STG.64
    #pragma unroll
    for (int idx = tid; idx < TR_ATOMS * NB2; idx += TPB) {
        int atom = idx >> 5;
        int l    = idx & 31;
        int ga = atom_base + atom;
        if (ga < n_atoms) {
            int a3 = atom * 3;
            float4* base = g_pos4 + (size_t)ga * ATOM_STRIDE4;
            base[l] = make_float4(tile[2 * l][a3], tile[2 * l + 1][a3],
                                  tile[2 * l][a3 + 1], tile[2 * l + 1][a3 + 1]);
            ((float2*)(base + NB2))[l] = make_float2(tile[2 * l][a3 + 2],
                                                     tile[2 * l + 1][a3 + 2]);
        }
    }
}

// ---- float2 elementwise helpers ----
__device__ __forceinline__ float2 f2sub(float2 a, float2 b) { return make_float2(a.x - b.x, a.y - b.y); }
__device__ __forceinline__ float2 f2mul(float2 a, float2 b) { return make_float2(a.x * b.x, a.y * b.y); }
__device__ __forceinline__ float2 f2fma(float2 a, float2 b, float2 c) {
    return make_float2(fmaf(a.x, b.x, c.x), fmaf(a.y, b.y, c.y));
}
__device__ __forceinline__ float2 f2nfma(float2 a, float2 b, float2 c) { // c - a*b
    return make_float2(fmaf(-a.x, b.x, c.x), fmaf(-a.y, b.y, c.y));
}
__device__ __forceinline__ float2 f2rsqrt(float2 a) { return make_float2(rsqrtf(a.x), rsqrtf(a.y)); }

__device__ __forceinline__ void load_atom(int a, int lane, float2& x, float2& y, float2& z) {
    const float4* base = g_pos4 + (size_t)a * ATOM_STRIDE4;
    float4 v = __ldg(base + lane);
    z = __ldg((const float2*)(base + NB2) + lane);
    x = make_float2(v.x, v.y);
    y = make_float2(v.z, v.w);
}

__device__ __forceinline__ float2 f2dot3(float2 ax, float2 ay, float2 az,
                                         float2 bx, float2 by, float2 bz) {
    return f2fma(ax, bx, f2fma(ay, by, f2mul(az, bz)));
}

// Abramowitz-Stegun 4.4.46 degree-7: |err| ~ 1e-7 over [-1, 1].
__device__ __forceinline__ float fast_acos(float x) {
    float a = fabsf(x);
    float p = fmaf(a, -0.0012624911f, 0.0066700901f);
    p = fmaf(a, p, -0.0170881256f);
    p = fmaf(a, p, 0.0308918810f);
    p = fmaf(a, p, -0.0501743046f);
    p = fmaf(a, p, 0.0889789874f);
    p = fmaf(a, p, -0.2145988016f);
    p = fmaf(a, p, 1.5707963050f);
    float r = p * sqrtf(1.0f - a);
    return (x < 0.0f) ? (3.14159265358979f - r) : r;
}

// Minimax odd atan on [0,1] + quadrant reduction; |err| ~ 1e-6.
__device__ __forceinline__ float fast_atan2(float y, float x) {
    float ax = fabsf(x), ay = fabsf(y);
    float mx = fmaxf(ax, ay), mn = fminf(ax, ay);
    float z = __fdividef(mn, mx);
    float z2 = z * z;
    float p = fmaf(z2, -0.0117212f, 0.0526533f);
    p = fmaf(z2, p, -0.1164329f);
    p = fmaf(z2, p, 0.1935435f);
    p = fmaf(z2, p, -0.3326235f);
    p = fmaf(z2, p, 0.9999773f);
    float r = p * z;
    if (ay > ax) r = 1.57079632679f - r;
    if (x < 0.0f) r = 3.14159265359f - r;
    return copysignf(r, y);
}

// Raw dihedral numerator/denominator (x, y) for a batch-pair; phi = atan2(y, x).
__device__ __forceinline__ void dihedral_xy(int a0, int a1, int a2, int a3, int lane,
                                            float2& X, float2& Y) {
    float2 x0, y0, z0, x1, y1, z1, x2, y2, z2, x3, y3, z3;
    load_atom(a0, lane, x0, y0, z0);
    load_atom(a1, lane, x1, y1, z1);
    load_atom(a2, lane, x2, y2, z2);
    load_atom(a3, lane, x3, y3, z3);
    float2 b0x = f2sub(x0, x1), b0y = f2sub(y0, y1), b0z = f2sub(z0, z1);
    float2 b1x = f2sub(x2, x1), b1y = f2sub(y2, y1), b1z = f2sub(z2, z1);
    float2 b2x = f2sub(x3, x2), b2y = f2sub(y3, y2), b2z = f2sub(z3, z2);
    float2 inv = f2rsqrt(f2dot3(b1x, b1y, b1z, b1x, b1y, b1z));
    b1x = f2mul(b1x, inv); b1y = f2mul(b1y, inv); b1z = f2mul(b1z, inv);
    float2 d0 = f2dot3(b0x, b0y, b0z, b1x, b1y, b1z);
    float2 d2 = f2dot3(b2x, b2y, b2z, b1x, b1y, b1z);
    float2 vx = f2nfma(d0, b1x, b0x), vy = f2nfma(d0, b1y, b0y), vz = f2nfma(d0, b1z, b0z);
    float2 wx = f2nfma(d2, b1x, b2x), wy = f2nfma(d2, b1y, b2y), wz = f2nfma(d2, b1z, b2z);
    X = f2dot3(vx, vy, vz, wx, wy, wz);
    float2 cx = f2sub(f2mul(b1y, vz), f2mul(b1z, vy));
    float2 cy = f2sub(f2mul(b1z, vx), f2mul(b1x, vz));
    float2 cz = f2sub(f2mul(b1x, vy), f2mul(b1y, vx));
    Y = f2dot3(cx, cy, cz, wx, wy, wz);
}

// All blocks walk ALL four categories as sequential tight loops with
// grid-wide warp stride: perfect load balance. Lane l covers batches 2l, 2l+1.
// Natural register allocation (no launch_bounds) — R14 showed forcing regs spills.
__global__ void energy_kernel(
    const int* __restrict__ bond_idcs, const int* __restrict__ bond_type,
    const float* __restrict__ equ_bond, const float* __restrict__ k_bond, int n_bond,
    const int* __restrict__ angle_idcs, const int* __restrict__ angle_type,
    const float* __restrict__ equ_angle, const float* __restrict__ k_angle, int n_angle,
    const int* __restrict__ improper_idcs, const int* __restrict__ improper_type,
    const float* __restrict__ equ_improper, const float* __restrict__ k_improper, int n_improper,
    const int* __restrict__ proper_idcs, const float* __restrict__ proper_phase,
    const float* __restrict__ proper_const, const float* __restrict__ proper_mul, int n_proper,
    float* __restrict__ out)
{
    int lane = threadIdx.x & 31;
    int warp = threadIdx.x >> 5;
    int warp_g = blockIdx.x * NWARP + warp;
    int nwarps = gridDim.x * NWARP;
    float ex = 0.0f, ey = 0.0f;

    // bonds
    for (int t = warp_g; t < n_bond; t += nwarps) {
        int a0 = __ldg(&bond_idcs[2 * t]);
        int a1 = __ldg(&bond_idcs[2 * t + 1]);
        int ty = __ldg(&bond_type[t]);
        float eq = __ldg(&equ_bond[ty]);
        float kb = __ldg(&k_bond[ty]);
        float2 x0, y0, z0, x1, y1, z1;
        load_atom(a0, lane, x0, y0, z0);
        load_atom(a1, lane, x1, y1, z1);
        float2 dx = f2sub(x0, x1), dy = f2sub(y0, y1), dz = f2sub(z0, z1);
        float2 r2 = f2dot3(dx, dy, dz, dx, dy, dz);
        float ddx = sqrtf(r2.x) - eq;
        float ddy = sqrtf(r2.y) - eq;
        ex = fmaf(kb * ddx, ddx, ex);
        ey = fmaf(kb * ddy, ddy, ey);
    }

    // angles
    for (int t = warp_g; t < n_angle; t += nwarps) {
        int a0 = __ldg(&angle_idcs[3 * t]);
        int a1 = __ldg(&angle_idcs[3 * t + 1]);
        int a2 = __ldg(&angle_idcs[3 * t + 2]);
        int ty = __ldg(&angle_type[t]);
        float eq = __ldg(&equ_angle[ty]);
        float ka = __ldg(&k_angle[ty]);
        float2 x0, y0, z0, x1, y1, z1, x2, y2, z2;
        load_atom(a0, lane, x0, y0, z0);
        load_atom(a1, lane, x1, y1, z1);
        load_atom(a2, lane, x2, y2, z2);
        float2 v1x = f2sub(x0, x1), v1y = f2sub(y0, y1), v1z = f2sub(z0, z1);
        float2 v2x = f2sub(x2, x1), v2y = f2sub(y2, y1), v2z = f2sub(z2, z1);
        float2 n1 = f2dot3(v1x, v1y, v1z, v1x, v1y, v1z);
        float2 n2 = f2dot3(v2x, v2y, v2z, v2x, v2y, v2z);
        float2 dt = f2dot3(v1x, v1y, v1z, v2x, v2y, v2z);
        float2 c = f2mul(f2mul(dt, f2rsqrt(n1)), f2rsqrt(n2));
        float cx = fminf(1.0f, fmaxf(-1.0f, c.x));
        float cy = fminf(1.0f, fmaxf(-1.0f, c.y));
        float ddx = fast_acos(cx) - eq;
        float ddy = fast_acos(cy) - eq;
        ex = fmaf(ka * ddx, ddx, ex);
        ey = fmaf(ka * ddy, ddy, ey);
    }

    // impropers
    for (int t = warp_g; t < n_improper; t += nwarps) {
        int4 a = __ldg((const int4*)improper_idcs + t);
        int ty = __ldg(&improper_type[t]);
        float eq = __ldg(&equ_improper[ty]);
        float ki = __ldg(&k_improper[ty]);
        float2 X, Y;
        dihedral_xy(a.x, a.y, a.z, a.w, lane, X, Y);
        float ddx = fast_atan2(Y.x, X.x) - eq;
        float ddy = fast_atan2(Y.y, X.y) - eq;
        ex = fmaf(ki * ddx, ddx, ex);
        ey = fmaf(ki * ddy, ddy, ey);
    }

    // propers
    for (int t = warp_g; t < n_proper; t += nwarps) {
        int4 a = __ldg((const int4*)proper_idcs + t);
        float ph  = __ldg(&proper_phase[t]);
        float cst = __ldg(&proper_const[t]);
        float ml  = __ldg(&proper_mul[t]);
        float2 X, Y;
        dihedral_xy(a.x, a.y, a.z, a.w, lane, X, Y);
        if (ml == 2.0f && ph == 0.0f) {
            // cst*(1+cos(2*atan2(y,x))) = 2*cst*x^2/(x^2+y^2)
            float c2x = 2.0f * cst;
            ex = fmaf(c2x * X.x, X.x / fmaf(X.x, X.x, Y.x * Y.x), ex);
            ey = fmaf(c2x * X.y, X.y / fmaf(X.y, X.y, Y.y * Y.y), ey);
        } else {
            float phix = fast_atan2(Y.x, X.x);
            float phiy = fast_atan2(Y.y, X.y);
            ex += cst * (1.0f + cosf(fmaf(ml, phix, -ph)));
            ey += cst * (1.0f + cosf(fmaf(ml, phiy, -ph)));
        }
    }

    // Per-warp private slots, then fold.
    __shared__ float sh[NWARP][NB];
    sh[warp][2 * lane]     = ex;
    sh[warp][2 * lane + 1] = ey;
    __syncthreads();
    if (threadIdx.x < NB) {
        float s = 0.0f;
        #pragma unroll
        for (int w = 0; w < NWARP; w++) s += sh[w][threadIdx.x];
        atomicAdd(&out[threadIdx.x], s);
    }
}

extern "C" void kernel_launch(void* const* d_in, const int* in_sizes, int n_in,
                              void* d_out, int out_size) {
    const float* pos            = (const float*)d_in[0];
    const int*   bond_idcs      = (const int*)d_in[1];
    const int*   bond_type      = (const int*)d_in[2];
    const float* equ_bond       = (const float*)d_in[3];
    const float* k_bond         = (const float*)d_in[4];
    const int*   angle_idcs     = (const int*)d_in[5];
    const int*   angle_type     = (const int*)d_in[6];
    const float* equ_angle      = (const float*)d_in[7];
    const float* k_angle        = (const float*)d_in[8];
    const int*   improper_idcs  = (const int*)d_in[9];
    const int*   improper_type  = (const int*)d_in[10];
    const float* equ_improper   = (const float*)d_in[11];
    const float* k_improper     = (const float*)d_in[12];
    const int*   proper_idcs    = (const int*)d_in[13];
    const float* proper_phase   = (const float*)d_in[14];
    const float* proper_const   = (const float*)d_in[15];
    const float* proper_mul     = (const float*)d_in[16];
    float* out = (float*)d_out;

    int B          = out_size;              // 64
    int n_bond     = in_sizes[2];
    int n_angle    = in_sizes[6];
    int n_improper = in_sizes[10];
    int n_proper   = in_sizes[14];
    int n_atoms    = in_sizes[0] / (3 * B);

    int tr_blocks = (n_atoms + TR_ATOMS - 1) / TR_ATOMS;
    transpose_kernel<<<tr_blocks, TPB>>>(pos, n_atoms, out);

    // Single wave: 888 blocks = 6 blocks/SM x 148 SMs (natural regs ~40-44).
    energy_kernel<<<888, TPB>>>(
        bond_idcs, bond_type, equ_bond, k_bond, n_bond,
        angle_idcs, angle_type, equ_angle, k_angle, n_angle,
        improper_idcs, improper_type, equ_improper, k_improper, n_improper,
        proper_idcs, proper_phase, proper_const, proper_mul, n_proper,
        out);
}

// round 16
// speedup vs baseline: 1.4728x; 1.4728x over previous
#include <cuda_runtime.h>
#include <cuda_bf16.h>

#define TPB 256
#define MAX_ATOMS 100000
#define NB 64
#define NB2 32   // float2 pairs per atom
#define NWARP (TPB / 32)
#define TR_ATOMS 32

// Interleaved batch-fastest positions: g_pos[atom][comp][pair] as float2.
// One address per atom; x/y/z at +0/+256/+512 bytes. Lane l covers batches
// 2l, 2l+1 -> every load is a coalesced 256B run.
__device__ float2 g_pos[(size_t)MAX_ATOMS * 3 * NB2];

// Tiled transpose: pos[b][atom][3] -> g_pos[atom][comp][pair]. Zeroes out[].
__global__ void transpose_kernel(const float* __restrict__ pos, int n_atoms,
                                 float* __restrict__ out) {
    __shared__ float tile[NB][TR_ATOMS * 3 + 1];   // [64][97]
    int tid = threadIdx.x;
    int atom_base = blockIdx.x * TR_ATOMS;

    if (blockIdx.x == 0 && tid < NB) out[tid] = 0.0f;

    int lim3 = n_atoms * 3;
    int base3 = atom_base * 3;
    #pragma unroll
    for (int idx = tid; idx < NB * (TR_ATOMS * 3 / 4); idx += TPB) {
        int b = idx / (TR_ATOMS * 3 / 4);
        int q = idx - b * (TR_ATOMS * 3 / 4);
        int g = base3 + q * 4;
        if (g + 3 < lim3) {
            float4 v = __ldg((const float4*)(pos + (size_t)b * lim3 + g));
            tile[b][q * 4]     = v.x;
            tile[b][q * 4 + 1] = v.y;
            tile[b][q * 4 + 2] = v.z;
            tile[b][q * 4 + 3] = v.w;
        } else {
            for (int k = 0; k < 4 && g + k < lim3; k++)
                tile[b][q * 4 + k] = __ldg(&pos[(size_t)b * lim3 + g + k]);
        }
    }
    __syncthreads();
    #pragma unroll
    for (int idx = tid; idx < 3 * TR_ATOMS * NB2; idx += TPB) {
        int comp = idx >> 10;
        int rem  = idx & 1023;
        int atom = rem >> 5;
        int l    = rem & 31;
        int ga = atom_base + atom;
        if (ga < n_atoms) {
            float2 v = make_float2(tile[2 * l][atom * 3 + comp],
                                   tile[2 * l + 1][atom * 3 + comp]);
            g_pos[(size_t)ga * (3 * NB2) + comp * NB2 + l] = v;
        }
    }
}

// ---- float2 elementwise helpers ----
__device__ __forceinline__ float2 f2sub(float2 a, float2 b) { return make_float2(a.x - b.x, a.y - b.y); }
__device__ __forceinline__ float2 f2mul(float2 a, float2 b) { return make_float2(a.x * b.x, a.y * b.y); }
__device__ __forceinline__ float2 f2fma(float2 a, float2 b, float2 c) {
    return make_float2(fmaf(a.x, b.x, c.x), fmaf(a.y, b.y, c.y));
}
__device__ __forceinline__ float2 f2nfma(float2 a, float2 b, float2 c) { // c - a*b
    return make_float2(fmaf(-a.x, b.x, c.x), fmaf(-a.y, b.y, c.y));
}
__device__ __forceinline__ float2 f2rsqrt(float2 a) { return make_float2(rsqrtf(a.x), rsqrtf(a.y)); }

__device__ __forceinline__ void load_atom(int a, int lane, float2& x, float2& y, float2& z) {
    const float2* p = g_pos + (size_t)a * (3 * NB2) + lane;
    x = __ldg(p);
    y = __ldg(p + NB2);
    z = __ldg(p + 2 * NB2);
}

__device__ __forceinline__ float2 f2dot3(float2 ax, float2 ay, float2 az,
                                         float2 bx, float2 by, float2 bz) {
    return f2fma(ax, bx, f2fma(ay, by, f2mul(az, bz)));
}

// Abramowitz-Stegun 4.4.46 degree-7: |err| ~ 1e-7 over [-1, 1].
__device__ __forceinline__ float fast_acos(float x) {
    float a = fabsf(x);
    float p = fmaf(a, -0.0012624911f, 0.0066700901f);
    p = fmaf(a, p, -0.0170881256f);
    p = fmaf(a, p, 0.0308918810f);
    p = fmaf(a, p, -0.0501743046f);
    p = fmaf(a, p, 0.0889789874f);
    p = fmaf(a, p, -0.2145988016f);
    p = fmaf(a, p, 1.5707963050f);
    float r = p * sqrtf(1.0f - a);
    return (x < 0.0f) ? (3.14159265358979f - r) : r;
}

// Minimax odd atan on [0,1] + quadrant reduction; |err| ~ 1e-6.
__device__ __forceinline__ float fast_atan2(float y, float x) {
    float ax = fabsf(x), ay = fabsf(y);
    float mx = fmaxf(ax, ay), mn = fminf(ax, ay);
    float z = __fdividef(mn, mx);
    float z2 = z * z;
    float p = fmaf(z2, -0.0117212f, 0.0526533f);
    p = fmaf(z2, p, -0.1164329f);
    p = fmaf(z2, p, 0.1935435f);
    p = fmaf(z2, p, -0.3326235f);
    p = fmaf(z2, p, 0.9999773f);
    float r = p * z;
    if (ay > ax) r = 1.57079632679f - r;
    if (x < 0.0f) r = 3.14159265359f - r;
    return copysignf(r, y);
}

// Raw dihedral numerator/denominator (x, y) for a batch-pair; phi = atan2(y, x).
__device__ __forceinline__ void dihedral_xy(int a0, int a1, int a2, int a3, int lane,
                                            float2& X, float2& Y) {
    float2 x0, y0, z0, x1, y1, z1, x2, y2, z2, x3, y3, z3;
    load_atom(a0, lane, x0, y0, z0);
    load_atom(a1, lane, x1, y1, z1);
    load_atom(a2, lane, x2, y2, z2);
    load_atom(a3, lane, x3, y3, z3);
    float2 b0x = f2sub(x0, x1), b0y = f2sub(y0, y1), b0z = f2sub(z0, z1);
    float2 b1x = f2sub(x2, x1), b1y = f2sub(y2, y1), b1z = f2sub(z2, z1);
    float2 b2x = f2sub(x3, x2), b2y = f2sub(y3, y2), b2z = f2sub(z3, z2);
    float2 inv = f2rsqrt(f2dot3(b1x, b1y, b1z, b1x, b1y, b1z));
    b1x = f2mul(b1x, inv); b1y = f2mul(b1y, inv); b1z = f2mul(b1z, inv);
    float2 d0 = f2dot3(b0x, b0y, b0z, b1x, b1y, b1z);
    float2 d2 = f2dot3(b2x, b2y, b2z, b1x, b1y, b1z);
    float2 vx = f2nfma(d0, b1x, b0x), vy = f2nfma(d0, b1y, b0y), vz = f2nfma(d0, b1z, b0z);
    float2 wx = f2nfma(d2, b1x, b2x), wy = f2nfma(d2, b1y, b2y), wz = f2nfma(d2, b1z, b2z);
    X = f2dot3(vx, vy, vz, wx, wy, wz);
    float2 cx = f2sub(f2mul(b1y, vz), f2mul(b1z, vy));
    float2 cy = f2sub(f2mul(b1z, vx), f2mul(b1x, vz));
    float2 cz = f2sub(f2mul(b1x, vy), f2mul(b1y, vx));
    Y = f2dot3(cx, cy, cz, wx, wy, wz);
}

// All blocks walk ALL four categories as sequential tight loops with
// grid-wide warp stride. 4x oversubscribed grid: short blocks + CTA-scheduler
// backfill absorb per-block completion-time spread. Lane l covers 2l, 2l+1.
__global__ void energy_kernel(
    const int* __restrict__ bond_idcs, const int* __restrict__ bond_type,
    const float* __restrict__ equ_bond, const float* __restrict__ k_bond, int n_bond,
    const int* __restrict__ angle_idcs, const int* __restrict__ angle_type,
    const float* __restrict__ equ_angle, const float* __restrict__ k_angle, int n_angle,
    const int* __restrict__ improper_idcs, const int* __restrict__ improper_type,
    const float* __restrict__ equ_improper, const float* __restrict__ k_improper, int n_improper,
    const int* __restrict__ proper_idcs, const float* __restrict__ proper_phase,
    const float* __restrict__ proper_const, const float* __restrict__ proper_mul, int n_proper,
    float* __restrict__ out)
{
    int lane = threadIdx.x & 31;
    int warp = threadIdx.x >> 5;
    int warp_g = blockIdx.x * NWARP + warp;
    int nwarps = gridDim.x * NWARP;
    float ex = 0.0f, ey = 0.0f;

    // bonds
    for (int t = warp_g; t < n_bond; t += nwarps) {
        int a0 = __ldg(&bond_idcs[2 * t]);
        int a1 = __ldg(&bond_idcs[2 * t + 1]);
        int ty = __ldg(&bond_type[t]);
        float eq = __ldg(&equ_bond[ty]);
        float kb = __ldg(&k_bond[ty]);
        float2 x0, y0, z0, x1, y1, z1;
        load_atom(a0, lane, x0, y0, z0);
        load_atom(a1, lane, x1, y1, z1);
        float2 dx = f2sub(x0, x1), dy = f2sub(y0, y1), dz = f2sub(z0, z1);
        float2 r2 = f2dot3(dx, dy, dz, dx, dy, dz);
        float ddx = sqrtf(r2.x) - eq;
        float ddy = sqrtf(r2.y) - eq;
        ex = fmaf(kb * ddx, ddx, ex);
        ey = fmaf(kb * ddy, ddy, ey);
    }

    // angles
    for (int t = warp_g; t < n_angle; t += nwarps) {
        int a0 = __ldg(&angle_idcs[3 * t]);
        int a1 = __ldg(&angle_idcs[3 * t + 1]);
        int a2 = __ldg(&angle_idcs[3 * t + 2]);
        int ty = __ldg(&angle_type[t]);
        float eq = __ldg(&equ_angle[ty]);
        float ka = __ldg(&k_angle[ty]);
        float2 x0, y0, z0, x1, y1, z1, x2, y2, z2;
        load_atom(a0, lane, x0, y0, z0);
        load_atom(a1, lane, x1, y1, z1);
        load_atom(a2, lane, x2, y2, z2);
        float2 v1x = f2sub(x0, x1), v1y = f2sub(y0, y1), v1z = f2sub(z0, z1);
        float2 v2x = f2sub(x2, x1), v2y = f2sub(y2, y1), v2z = f2sub(z2, z1);
        float2 n1 = f2dot3(v1x, v1y, v1z, v1x, v1y, v1z);
        float2 n2 = f2dot3(v2x, v2y, v2z, v2x, v2y, v2z);
        float2 dt = f2dot3(v1x, v1y, v1z, v2x, v2y, v2z);
        float2 c = f2mul(f2mul(dt, f2rsqrt(n1)), f2rsqrt(n2));
        float cx = fminf(1.0f, fmaxf(-1.0f, c.x));
        float cy = fminf(1.0f, fmaxf(-1.0f, c.y));
        float ddx = fast_acos(cx) - eq;
        float ddy = fast_acos(cy) - eq;
        ex = fmaf(ka * ddx, ddx, ex);
        ey = fmaf(ka * ddy, ddy, ey);
    }

    // impropers
    for (int t = warp_g; t < n_improper; t += nwarps) {
        int4 a = __ldg((const int4*)improper_idcs + t);
        int ty = __ldg(&improper_type[t]);
        float eq = __ldg(&equ_improper[ty]);
        float ki = __ldg(&k_improper[ty]);
        float2 X, Y;
        dihedral_xy(a.x, a.y, a.z, a.w, lane, X, Y);
        float ddx = fast_atan2(Y.x, X.x) - eq;
        float ddy = fast_atan2(Y.y, X.y) - eq;
        ex = fmaf(ki * ddx, ddx, ex);
        ey = fmaf(ki * ddy, ddy, ey);
    }

    // propers
    for (int t = warp_g; t < n_proper; t += nwarps) {
        int4 a = __ldg((const int4*)proper_idcs + t);
        float ph  = __ldg(&proper_phase[t]);
        float cst = __ldg(&proper_const[t]);
        float ml  = __ldg(&proper_mul[t]);
        float2 X, Y;
        dihedral_xy(a.x, a.y, a.z, a.w, lane, X, Y);
        if (ml == 2.0f && ph == 0.0f) {
            // cst*(1+cos(2*atan2(y,x))) = 2*cst*x^2/(x^2+y^2)
            float c2x = 2.0f * cst;
            ex = fmaf(c2x * X.x, X.x / fmaf(X.x, X.x, Y.x * Y.x), ex);
            ey = fmaf(c2x * X.y, X.y / fmaf(X.y, X.y, Y.y * Y.y), ey);
        } else {
            float phix = fast_atan2(Y.x, X.x);
            float phiy = fast_atan2(Y.y, X.y);
            ex += cst * (1.0f + cosf(fmaf(ml, phix, -ph)));
            ey += cst * (1.0f + cosf(fmaf(ml, phiy, -ph)));
        }
    }

    // Per-warp private slots, then fold.
    __shared__ float sh[NWARP][NB];
    sh[warp][2 * lane]     = ex;
    sh[warp][2 * lane + 1] = ey;
    __syncthreads();
    if (threadIdx.x < NB) {
        float s = 0.0f;
        #pragma unroll
        for (int w = 0; w < NWARP; w++) s += sh[w][threadIdx.x];
        atomicAdd(&out[threadIdx.x], s);
    }
}

extern "C" void kernel_launch(void* const* d_in, const int* in_sizes, int n_in,
                              void* d_out, int out_size) {
    const float* pos            = (const float*)d_in[0];
    const int*   bond_idcs      = (const int*)d_in[1];
    const int*   bond_type      = (const int*)d_in[2];
    const float* equ_bond       = (const float*)d_in[3];
    const float* k_bond         = (const float*)d_in[4];
    const int*   angle_idcs     = (const int*)d_in[5];
    const int*   angle_type     = (const int*)d_in[6];
    const float* equ_angle      = (const float*)d_in[7];
    const float* k_angle        = (const float*)d_in[8];
    const int*   improper_idcs  = (const int*)d_in[9];
    const int*   improper_type  = (const int*)d_in[10];
    const float* equ_improper   = (const float*)d_in[11];
    const float* k_improper     = (const float*)d_in[12];
    const int*   proper_idcs    = (const int*)d_in[13];
    const float* proper_phase   = (const float*)d_in[14];
    const float* proper_const   = (const float*)d_in[15];
    const float* proper_mul     = (const float*)d_in[16];
    float* out = (float*)d_out;

    int B          = out_size;              // 64
    int n_bond     = in_sizes[2];
    int n_angle    = in_sizes[6];
    int n_improper = in_sizes[10];
    int n_proper   = in_sizes[14];
    int n_atoms    = in_sizes[0] / (3 * B);

    int tr_blocks = (n_atoms + TR_ATOMS - 1) / TR_ATOMS;
    transpose_kernel<<<tr_blocks, TPB>>>(pos, n_atoms, out);

    // 3552 blocks = 4 waves of 6 blocks/SM: short blocks + backfill absorb
    // per-block completion-time spread (R13 single wave showed occ 65.7%).
    energy_kernel<<<3552, TPB>>>(
        bond_idcs, bond_type, equ_bond, k_bond, n_bond,
        angle_idcs, angle_type, equ_angle, k_angle, n_angle,
        improper_idcs, improper_type, equ_improper, k_improper, n_improper,
        proper_idcs, proper_phase, proper_const, proper_mul, n_proper,
        out);
}

// round 17
// speedup vs baseline: 1.5187x; 1.0312x over previous
#include <cuda_runtime.h>
#include <cuda_bf16.h>

#define TPB 256
#define MAX_ATOMS 100000
#define NB 64
#define NB2 32   // float2 pairs per atom
#define NWARP (TPB / 32)
#define TR_ATOMS 32

// Interleaved batch-fastest positions: g_pos[atom][comp][pair] as float2.
// One address per atom; x/y/z at +0/+256/+512 bytes. Lane l covers batches
// 2l, 2l+1 -> every load is a coalesced 256B run.
__device__ float2 g_pos[(size_t)MAX_ATOMS * 3 * NB2];

// Tiled transpose: pos[b][atom][3] -> g_pos[atom][comp][pair]. Zeroes out[].
__global__ void transpose_kernel(const float* __restrict__ pos, int n_atoms,
                                 float* __restrict__ out) {
    __shared__ float tile[NB][TR_ATOMS * 3 + 1];   // [64][97]
    int tid = threadIdx.x;
    int atom_base = blockIdx.x * TR_ATOMS;

    if (blockIdx.x == 0 && tid < NB) out[tid] = 0.0f;

    int lim3 = n_atoms * 3;
    int base3 = atom_base * 3;
    #pragma unroll
    for (int idx = tid; idx < NB * (TR_ATOMS * 3 / 4); idx += TPB) {
        int b = idx / (TR_ATOMS * 3 / 4);
        int q = idx - b * (TR_ATOMS * 3 / 4);
        int g = base3 + q * 4;
        if (g + 3 < lim3) {
            float4 v = __ldg((const float4*)(pos + (size_t)b * lim3 + g));
            tile[b][q * 4]     = v.x;
            tile[b][q * 4 + 1] = v.y;
            tile[b][q * 4 + 2] = v.z;
            tile[b][q * 4 + 3] = v.w;
        } else {
            for (int k = 0; k < 4 && g + k < lim3; k++)
                tile[b][q * 4 + k] = __ldg(&pos[(size_t)b * lim3 + g + k]);
        }
    }
    __syncthreads();
    #pragma unroll
    for (int idx = tid; idx < 3 * TR_ATOMS * NB2; idx += TPB) {
        int comp = idx >> 10;
        int rem  = idx & 1023;
        int atom = rem >> 5;
        int l    = rem & 31;
        int ga = atom_base + atom;
        if (ga < n_atoms) {
            float2 v = make_float2(tile[2 * l][atom * 3 + comp],
                                   tile[2 * l + 1][atom * 3 + comp]);
            g_pos[(size_t)ga * (3 * NB2) + comp * NB2 + l] = v;
        }
    }
}

// ---- float2 elementwise helpers ----
__device__ __forceinline__ float2 f2sub(float2 a, float2 b) { return make_float2(a.x - b.x, a.y - b.y); }
__device__ __forceinline__ float2 f2mul(float2 a, float2 b) { return make_float2(a.x * b.x, a.y * b.y); }
__device__ __forceinline__ float2 f2fma(float2 a, float2 b, float2 c) {
    return make_float2(fmaf(a.x, b.x, c.x), fmaf(a.y, b.y, c.y));
}
__device__ __forceinline__ float2 f2nfma(float2 a, float2 b, float2 c) { // c - a*b
    return make_float2(fmaf(-a.x, b.x, c.x), fmaf(-a.y, b.y, c.y));
}
__device__ __forceinline__ float2 f2rsqrt(float2 a) { return make_float2(rsqrtf(a.x), rsqrtf(a.y)); }

__device__ __forceinline__ void load_atom(int a, int lane, float2& x, float2& y, float2& z) {
    const float2* p = g_pos + (size_t)a * (3 * NB2) + lane;
    x = __ldg(p);
    y = __ldg(p + NB2);
    z = __ldg(p + 2 * NB2);
}

__device__ __forceinline__ float2 f2dot3(float2 ax, float2 ay, float2 az,
                                         float2 bx, float2 by, float2 bz) {
    return f2fma(ax, bx, f2fma(ay, by, f2mul(az, bz)));
}

// Abramowitz-Stegun 4.4.46 degree-7: |err| ~ 1e-7 over [-1, 1].
__device__ __forceinline__ float fast_acos(float x) {
    float a = fabsf(x);
    float p = fmaf(a, -0.0012624911f, 0.0066700901f);
    p = fmaf(a, p, -0.0170881256f);
    p = fmaf(a, p, 0.0308918810f);
    p = fmaf(a, p, -0.0501743046f);
    p = fmaf(a, p, 0.0889789874f);
    p = fmaf(a, p, -0.2145988016f);
    p = fmaf(a, p, 1.5707963050f);
    float r = p * sqrtf(1.0f - a);
    return (x < 0.0f) ? (3.14159265358979f - r) : r;
}

// Minimax odd atan on [0,1] + quadrant reduction; |err| ~ 1e-6.
__device__ __forceinline__ float fast_atan2(float y, float x) {
    float ax = fabsf(x), ay = fabsf(y);
    float mx = fmaxf(ax, ay), mn = fminf(ax, ay);
    float z = __fdividef(mn, mx);
    float z2 = z * z;
    float p = fmaf(z2, -0.0117212f, 0.0526533f);
    p = fmaf(z2, p, -0.1164329f);
    p = fmaf(z2, p, 0.1935435f);
    p = fmaf(z2, p, -0.3326235f);
    p = fmaf(z2, p, 0.9999773f);
    float r = p * z;
    if (ay > ax) r = 1.57079632679f - r;
    if (x < 0.0f) r = 3.14159265359f - r;
    return copysignf(r, y);
}

// Raw dihedral numerator/denominator (x, y) for a batch-pair; phi = atan2(y, x).
__device__ __forceinline__ void dihedral_xy(int a0, int a1, int a2, int a3, int lane,
                                            float2& X, float2& Y) {
    float2 x0, y0, z0, x1, y1, z1, x2, y2, z2, x3, y3, z3;
    load_atom(a0, lane, x0, y0, z0);
    load_atom(a1, lane, x1, y1, z1);
    load_atom(a2, lane, x2, y2, z2);
    load_atom(a3, lane, x3, y3, z3);
    float2 b0x = f2sub(x0, x1), b0y = f2sub(y0, y1), b0z = f2sub(z0, z1);
    float2 b1x = f2sub(x2, x1), b1y = f2sub(y2, y1), b1z = f2sub(z2, z1);
    float2 b2x = f2sub(x3, x2), b2y = f2sub(y3, y2), b2z = f2sub(z3, z2);
    float2 inv = f2rsqrt(f2dot3(b1x, b1y, b1z, b1x, b1y, b1z));
    b1x = f2mul(b1x, inv); b1y = f2mul(b1y, inv); b1z = f2mul(b1z, inv);
    float2 d0 = f2dot3(b0x, b0y, b0z, b1x, b1y, b1z);
    float2 d2 = f2dot3(b2x, b2y, b2z, b1x, b1y, b1z);
    float2 vx = f2nfma(d0, b1x, b0x), vy = f2nfma(d0, b1y, b0y), vz = f2nfma(d0, b1z, b0z);
    float2 wx = f2nfma(d2, b1x, b2x), wy = f2nfma(d2, b1y, b2y), wz = f2nfma(d2, b1z, b2z);
    X = f2dot3(vx, vy, vz, wx, wy, wz);
    float2 cx = f2sub(f2mul(b1y, vz), f2mul(b1z, vy));
    float2 cy = f2sub(f2mul(b1z, vx), f2mul(b1x, vz));
    float2 cz = f2sub(f2mul(b1x, vy), f2mul(b1y, vx));
    Y = f2dot3(cx, cy, cz, wx, wy, wz);
}

// All blocks walk ALL four categories as sequential tight loops with
// grid-wide warp stride. Oversubscribed grid: short blocks + CTA-scheduler
// backfill absorb per-block completion-time spread. Lane l covers 2l, 2l+1.
__global__ void energy_kernel(
    const int* __restrict__ bond_idcs, const int* __restrict__ bond_type,
    const float* __restrict__ equ_bond, const float* __restrict__ k_bond, int n_bond,
    const int* __restrict__ angle_idcs, const int* __restrict__ angle_type,
    const float* __restrict__ equ_angle, const float* __restrict__ k_angle, int n_angle,
    const int* __restrict__ improper_idcs, const int* __restrict__ improper_type,
    const float* __restrict__ equ_improper, const float* __restrict__ k_improper, int n_improper,
    const int* __restrict__ proper_idcs, const float* __restrict__ proper_phase,
    const float* __restrict__ proper_const, const float* __restrict__ proper_mul, int n_proper,
    float* __restrict__ out)
{
    int lane = threadIdx.x & 31;
    int warp = threadIdx.x >> 5;
    int warp_g = blockIdx.x * NWARP + warp;
    int nwarps = gridDim.x * NWARP;
    float ex = 0.0f, ey = 0.0f;

    // bonds
    for (int t = warp_g; t < n_bond; t += nwarps) {
        int a0 = __ldg(&bond_idcs[2 * t]);
        int a1 = __ldg(&bond_idcs[2 * t + 1]);
        int ty = __ldg(&bond_type[t]);
        float eq = __ldg(&equ_bond[ty]);
        float kb = __ldg(&k_bond[ty]);
        float2 x0, y0, z0, x1, y1, z1;
        load_atom(a0, lane, x0, y0, z0);
        load_atom(a1, lane, x1, y1, z1);
        float2 dx = f2sub(x0, x1), dy = f2sub(y0, y1), dz = f2sub(z0, z1);
        float2 r2 = f2dot3(dx, dy, dz, dx, dy, dz);
        float ddx = sqrtf(r2.x) - eq;
        float ddy = sqrtf(r2.y) - eq;
        ex = fmaf(kb * ddx, ddx, ex);
        ey = fmaf(kb * ddy, ddy, ey);
    }

    // angles
    for (int t = warp_g; t < n_angle; t += nwarps) {
        int a0 = __ldg(&angle_idcs[3 * t]);
        int a1 = __ldg(&angle_idcs[3 * t + 1]);
        int a2 = __ldg(&angle_idcs[3 * t + 2]);
        int ty = __ldg(&angle_type[t]);
        float eq = __ldg(&equ_angle[ty]);
        float ka = __ldg(&k_angle[ty]);
        float2 x0, y0, z0, x1, y1, z1, x2, y2, z2;
        load_atom(a0, lane, x0, y0, z0);
        load_atom(a1, lane, x1, y1, z1);
        load_atom(a2, lane, x2, y2, z2);
        float2 v1x = f2sub(x0, x1), v1y = f2sub(y0, y1), v1z = f2sub(z0, z1);
        float2 v2x = f2sub(x2, x1), v2y = f2sub(y2, y1), v2z = f2sub(z2, z1);
        float2 n1 = f2dot3(v1x, v1y, v1z, v1x, v1y, v1z);
        float2 n2 = f2dot3(v2x, v2y, v2z, v2x, v2y, v2z);
        float2 dt = f2dot3(v1x, v1y, v1z, v2x, v2y, v2z);
        // one MUFU: rsqrt(n1*n2) instead of rsqrt(n1)*rsqrt(n2)
        float2 c = f2mul(dt, f2rsqrt(f2mul(n1, n2)));
        float cx = fminf(1.0f, fmaxf(-1.0f, c.x));
        float cy = fminf(1.0f, fmaxf(-1.0f, c.y));
        float ddx = fast_acos(cx) - eq;
        float ddy = fast_acos(cy) - eq;
        ex = fmaf(ka * ddx, ddx, ex);
        ey = fmaf(ka * ddy, ddy, ey);
    }

    // impropers
    for (int t = warp_g; t < n_improper; t += nwarps) {
        int4 a = __ldg((const int4*)improper_idcs + t);
        int ty = __ldg(&improper_type[t]);
        float eq = __ldg(&equ_improper[ty]);
        float ki = __ldg(&k_improper[ty]);
        float2 X, Y;
        dihedral_xy(a.x, a.y, a.z, a.w, lane, X, Y);
        float ddx = fast_atan2(Y.x, X.x) - eq;
        float ddy = fast_atan2(Y.y, X.y) - eq;
        ex = fmaf(ki * ddx, ddx, ex);
        ey = fmaf(ki * ddy, ddy, ey);
    }

    // propers
    for (int t = warp_g; t < n_proper; t += nwarps) {
        int4 a = __ldg((const int4*)proper_idcs + t);
        float ph  = __ldg(&proper_phase[t]);
        float cst = __ldg(&proper_const[t]);
        float ml  = __ldg(&proper_mul[t]);
        float2 X, Y;
        dihedral_xy(a.x, a.y, a.z, a.w, lane, X, Y);
        if (ml == 2.0f && ph == 0.0f) {
            // cst*(1+cos(2*atan2(y,x))) = 2*cst*x^2/(x^2+y^2); fast divide
            float c2x = 2.0f * cst;
            ex = fmaf(c2x * X.x, __fdividef(X.x, fmaf(X.x, X.x, Y.x * Y.x)), ex);
            ey = fmaf(c2x * X.y, __fdividef(X.y, fmaf(X.y, X.y, Y.y * Y.y)), ey);
        } else {
            float phix = fast_atan2(Y.x, X.x);
            float phiy = fast_atan2(Y.y, X.y);
            ex += cst * (1.0f + cosf(fmaf(ml, phix, -ph)));
            ey += cst * (1.0f + cosf(fmaf(ml, phiy, -ph)));
        }
    }

    // Per-warp private slots, then fold.
    __shared__ float sh[NWARP][NB];
    sh[warp][2 * lane]     = ex;
    sh[warp][2 * lane + 1] = ey;
    __syncthreads();
    if (threadIdx.x < NB) {
        float s = 0.0f;
        #pragma unroll
        for (int w = 0; w < NWARP; w++) s += sh[w][threadIdx.x];
        atomicAdd(&out[threadIdx.x], s);
    }
}

extern "C" void kernel_launch(void* const* d_in, const int* in_sizes, int n_in,
                              void* d_out, int out_size) {
    const float* pos            = (const float*)d_in[0];
    const int*   bond_idcs      = (const int*)d_in[1];
    const int*   bond_type      = (const int*)d_in[2];
    const float* equ_bond       = (const float*)d_in[3];
    const float* k_bond         = (const float*)d_in[4];
    const int*   angle_idcs     = (const int*)d_in[5];
    const int*   angle_type     = (const int*)d_in[6];
    const float* equ_angle      = (const float*)d_in[7];
    const float* k_angle        = (const float*)d_in[8];
    const int*   improper_idcs  = (const int*)d_in[9];
    const int*   improper_type  = (const int*)d_in[10];
    const float* equ_improper   = (const float*)d_in[11];
    const float* k_improper     = (const float*)d_in[12];
    const int*   proper_idcs    = (const int*)d_in[13];
    const float* proper_phase   = (const float*)d_in[14];
    const float* proper_const   = (const float*)d_in[15];
    const float* proper_mul     = (const float*)d_in[16];
    float* out = (float*)d_out;

    int B          = out_size;              // 64
    int n_bond     = in_sizes[2];
    int n_angle    = in_sizes[6];
    int n_improper = in_sizes[10];
    int n_proper   = in_sizes[14];
    int n_atoms    = in_sizes[0] / (3 * B);

    int tr_blocks = (n_atoms + TR_ATOMS - 1) / TR_ATOMS;
    transpose_kernel<<<tr_blocks, TPB>>>(pos, n_atoms, out);

    // 5328 blocks = 6 waves of 6 blocks/SM: short blocks + backfill absorb
    // per-block completion-time spread.
    energy_kernel<<<5328, TPB>>>(
        bond_idcs, bond_type, equ_bond, k_bond, n_bond,
        angle_idcs, angle_type, equ_angle, k_angle, n_angle,
        improper_idcs, improper_type, equ_improper, k_improper, n_improper,
        proper_idcs, proper_phase, proper_const, proper_mul, n_proper,
        out);
}